// round 15
// baseline (speedup 1.0000x reference)
#include <cuda_runtime.h>
#include <cuda_fp16.h>

#define EMBED_DIM   256
#define NUM_EDGES   16384
#define NUM_NODES   100000
#define NTHREADS    128
#define WARPS_CTA   (NTHREADS / 32)
#define AGG_BLOCKS  2048   // persistent-ish: 8192 warps, each steals edges

#define CONV_GROUPS (NUM_NODES * EMBED_DIM / 8)   // 3,200,000 groups of 8 floats
#define CONV_BLOCKS (CONV_GROUPS / 256)           // 12,500

// fp16 shadow of the embedding table (51.2 MB) — sanctioned __device__ scratch.
__device__ __half g_emb_h[(size_t)NUM_NODES * EMBED_DIM];
// g_offs[e] = lower_bound(seg, e); g_offs[NUM_EDGES] = total.
__device__ int g_offs[NUM_EDGES + 1];
// Work-stealing cursor for agg (reset by prep each call -> deterministic replay).
__device__ int g_edge_ctr;

__device__ __forceinline__ unsigned h2_bits(__half2 h)
{
    unsigned u;
    *reinterpret_cast<__half2*>(&u) = h;
    return u;
}

// Fused prepass: blocks [0, CONV_BLOCKS) convert fp32 -> fp16 at 8 floats/
// thread; remaining blocks fill segment bounds. Block 0 resets the cursor.
__global__ void __launch_bounds__(256)
prep_kernel(const float* __restrict__ emb, const int* __restrict__ seg, int total)
{
    const int b = blockIdx.x;
    if (b == 0 && threadIdx.x == 0) g_edge_ctr = 0;
    if (b < CONV_BLOCKS) {
        const int i = b * 256 + threadIdx.x;           // group of 8 floats
        const float4* src = (const float4*)emb;
        float4 a = __ldcs(src + 2 * (size_t)i);
        float4 c = __ldcs(src + 2 * (size_t)i + 1);
        uint4 o;
        o.x = h2_bits(__floats2half2_rn(a.x, a.y));
        o.y = h2_bits(__floats2half2_rn(a.z, a.w));
        o.z = h2_bits(__floats2half2_rn(c.x, c.y));
        o.w = h2_bits(__floats2half2_rn(c.z, c.w));
        ((uint4*)g_emb_h)[i] = o;
    } else {
        const int i = (b - CONV_BLOCKS) * 256 + threadIdx.x;
        if (i >= total) return;
        int cur = seg[i];
        if (i == 0) {
            for (int e = 0; e <= cur; e++) g_offs[e] = 0;
        } else {
            int prev = seg[i - 1];
            for (int e = prev + 1; e <= cur; e++) g_offs[e] = i;
        }
        if (i == total - 1) {
            for (int e = cur + 1; e <= NUM_EDGES; e++) g_offs[e] = total;
        }
    }
}

// 16-byte gather (non-volatile: let ptxas batch/hoist).
__device__ __forceinline__ ulonglong2 ldg16(const ulonglong2* p)
{
    ulonglong2 v;
    asm("ld.global.nc.v2.b64 {%0,%1}, [%2];"
        : "=l"(v.x), "=l"(v.y) : "l"(p));
    return v;
}

__device__ __forceinline__ int ldg_cs(const int* p)
{
    int v;
    asm volatile("ld.global.cs.b32 %0, [%1];" : "=r"(v) : "l"(p));
    return v;
}

__device__ __forceinline__ void stg_cs8(ulonglong4* p, const ulonglong4 v)
{
    asm volatile("st.global.cs.v4.b64 [%0], {%1,%2,%3,%4};"
                 :: "l"(p), "l"(v.x), "l"(v.y), "l"(v.z), "l"(v.w));
}

// Pairwise fp16 add of two 16B chunks (4 HADD2).
__device__ __forceinline__ ulonglong2 hpair(const ulonglong2 a, const ulonglong2 b)
{
    ulonglong2 r;
    const __half2* ha = (const __half2*)&a;
    const __half2* hb = (const __half2*)&b;
    __half2* hr = (__half2*)&r;
#pragma unroll
    for (int k = 0; k < 4; k++) hr[k] = __hadd2(ha[k], hb[k]);
    return r;
}

// Accumulate 8 fp16 values (one 16B chunk) into fp32 accumulators.
__device__ __forceinline__ void acch(float* a, const ulonglong2 v)
{
    const __half2* h = (const __half2*)&v;
#pragma unroll
    for (int k = 0; k < 4; k++) {
        float2 f = __half22float2(h[k]);
        a[2 * k]     += f.x;
        a[2 * k + 1] += f.y;
    }
}

// Warp-level work stealing over hyperedges: each warp atomically grabs the
// next edge, so all warps finish within ~one edge of each other (kills the
// per-CTA straggler loss and the last-wave tail). Gather loop = R13 best:
// lane c owns 16B chunk c; 8-member unroll; HADD2 pairwise pre-add.
__global__ void __launch_bounds__(NTHREADS)
agg_kernel(const int* __restrict__ nidx,   // [TOTAL]
           float*     __restrict__ out)    // [NUM_EDGES, 256]
{
    const int lane = threadIdx.x & 31;
    const ulonglong2* __restrict__ rows = (const ulonglong2*)g_emb_h; // 32 chunks/row

    for (;;) {
        int e;
        if (lane == 0) e = atomicAdd(&g_edge_ctr, 1);
        e = __shfl_sync(0xffffffffu, e, 0);
        if (e >= NUM_EDGES) return;

        const int lo = g_offs[e];
        const int hi = g_offs[e + 1];

        float acc[8];
#pragma unroll
        for (int k = 0; k < 8; k++) acc[k] = 0.0f;

        // Pipelined index loads: prefetch next chunk while gathering current.
        int myidx = 0;
        if (lo + lane < hi) myidx = ldg_cs(nidx + lo + lane);

        for (int base = lo; base < hi; base += 32) {
            const int cnt = min(32, hi - base);
            const int cur = myidx;
            if (base + 32 + lane < hi) myidx = ldg_cs(nidx + base + 32 + lane);

            int j = 0;
            // 8 members per iteration -> 8 independent 16B gathers in flight/lane.
            for (; j + 8 <= cnt; j += 8) {
                const int n0 = __shfl_sync(0xffffffffu, cur, j);
                const int n1 = __shfl_sync(0xffffffffu, cur, j + 1);
                const int n2 = __shfl_sync(0xffffffffu, cur, j + 2);
                const int n3 = __shfl_sync(0xffffffffu, cur, j + 3);
                const int n4 = __shfl_sync(0xffffffffu, cur, j + 4);
                const int n5 = __shfl_sync(0xffffffffu, cur, j + 5);
                const int n6 = __shfl_sync(0xffffffffu, cur, j + 6);
                const int n7 = __shfl_sync(0xffffffffu, cur, j + 7);
                ulonglong2 v0 = ldg16(rows + (size_t)n0 * 32 + lane);
                ulonglong2 v1 = ldg16(rows + (size_t)n1 * 32 + lane);
                ulonglong2 v2 = ldg16(rows + (size_t)n2 * 32 + lane);
                ulonglong2 v3 = ldg16(rows + (size_t)n3 * 32 + lane);
                ulonglong2 v4 = ldg16(rows + (size_t)n4 * 32 + lane);
                ulonglong2 v5 = ldg16(rows + (size_t)n5 * 32 + lane);
                ulonglong2 v6 = ldg16(rows + (size_t)n6 * 32 + lane);
                ulonglong2 v7 = ldg16(rows + (size_t)n7 * 32 + lane);
                acch(acc, hpair(v0, v1));
                acch(acc, hpair(v2, v3));
                acch(acc, hpair(v4, v5));
                acch(acc, hpair(v6, v7));
            }
            // Simple serial tail (keeps register pressure low).
            for (; j < cnt; j++) {
                const int n = __shfl_sync(0xffffffffu, cur, j);
                acch(acc, ldg16(rows + (size_t)n * 32 + lane));
            }
        }

        const int cnt = hi - lo;
        const float inv = 1.0f / (float)(cnt > 0 ? cnt : 1);
#pragma unroll
        for (int k = 0; k < 8; k++) acc[k] *= inv;

        // Lane c owns fp32 columns [8c, 8c+8) -> one 32B store.
        ulonglong4 r;
        float* f = (float*)&r;
#pragma unroll
        for (int k = 0; k < 8; k++) f[k] = acc[k];
        stg_cs8((ulonglong4*)out + (size_t)e * 32 + lane, r);
    }
}

extern "C" void kernel_launch(void* const* d_in, const int* in_sizes, int n_in,
                              void* d_out, int out_size)
{
    const float* emb  = (const float*)d_in[0];
    const int*   nidx = (const int*)d_in[1];
    const int*   seg  = (const int*)d_in[2];
    float*       out  = (float*)d_out;
    const int total = in_sizes[1];

    const int bounds_blocks = (total + 255) / 256;
    prep_kernel<<<CONV_BLOCKS + bounds_blocks, 256>>>(emb, seg, total);
    agg_kernel<<<AGG_BLOCKS, NTHREADS>>>(nidx, out);
}

// round 16
// speedup vs baseline: 1.2167x; 1.2167x over previous
#include <cuda_runtime.h>
#include <cuda_fp16.h>

#define EMBED_DIM   256
#define NUM_EDGES   16384
#define NUM_NODES   100000
#define NTHREADS    64                       // 2 warps/CTA: fine backfill + 42 warps/SM
#define WARPS_CTA   (NTHREADS / 32)

#define CONV_GROUPS (NUM_NODES * EMBED_DIM / 8)   // 3,200,000 groups of 8 floats
#define CONV_BLOCKS (CONV_GROUPS / 256)           // 12,500

// fp16 shadow of the embedding table (51.2 MB) — sanctioned __device__ scratch.
__device__ __half g_emb_h[(size_t)NUM_NODES * EMBED_DIM];
// g_offs[e] = lower_bound(seg, e); g_offs[NUM_EDGES] = total.
__device__ int g_offs[NUM_EDGES + 1];

__device__ __forceinline__ unsigned h2_bits(__half2 h)
{
    unsigned u;
    *reinterpret_cast<__half2*>(&u) = h;
    return u;
}

// Fused prepass (measured-best config): blocks [0, CONV_BLOCKS) convert
// fp32 -> fp16 at 8 floats/thread; remaining blocks fill segment bounds.
__global__ void __launch_bounds__(256)
prep_kernel(const float* __restrict__ emb, const int* __restrict__ seg, int total)
{
    const int b = blockIdx.x;
    if (b < CONV_BLOCKS) {
        const int i = b * 256 + threadIdx.x;           // group of 8 floats
        const float4* src = (const float4*)emb;
        float4 a = __ldcs(src + 2 * (size_t)i);
        float4 c = __ldcs(src + 2 * (size_t)i + 1);
        uint4 o;
        o.x = h2_bits(__floats2half2_rn(a.x, a.y));
        o.y = h2_bits(__floats2half2_rn(a.z, a.w));
        o.z = h2_bits(__floats2half2_rn(c.x, c.y));
        o.w = h2_bits(__floats2half2_rn(c.z, c.w));
        ((uint4*)g_emb_h)[i] = o;
    } else {
        const int i = (b - CONV_BLOCKS) * 256 + threadIdx.x;
        if (i >= total) return;
        int cur = seg[i];
        if (i == 0) {
            for (int e = 0; e <= cur; e++) g_offs[e] = 0;
        } else {
            int prev = seg[i - 1];
            for (int e = prev + 1; e <= cur; e++) g_offs[e] = i;
        }
        if (i == total - 1) {
            for (int e = cur + 1; e <= NUM_EDGES; e++) g_offs[e] = total;
        }
    }
}

// 16-byte gather (non-volatile: let ptxas batch/hoist).
__device__ __forceinline__ ulonglong2 ldg16(const ulonglong2* p)
{
    ulonglong2 v;
    asm("ld.global.nc.v2.b64 {%0,%1}, [%2];"
        : "=l"(v.x), "=l"(v.y) : "l"(p));
    return v;
}

__device__ __forceinline__ int ldg_cs(const int* p)
{
    int v;
    asm volatile("ld.global.cs.b32 %0, [%1];" : "=r"(v) : "l"(p));
    return v;
}

__device__ __forceinline__ void stg_cs8(ulonglong4* p, const ulonglong4 v)
{
    asm volatile("st.global.cs.v4.b64 [%0], {%1,%2,%3,%4};"
                 :: "l"(p), "l"(v.x), "l"(v.y), "l"(v.z), "l"(v.w));
}

// Pairwise fp16 add of two 16B chunks (4 HADD2).
__device__ __forceinline__ ulonglong2 hpair(const ulonglong2 a, const ulonglong2 b)
{
    ulonglong2 r;
    const __half2* ha = (const __half2*)&a;
    const __half2* hb = (const __half2*)&b;
    __half2* hr = (__half2*)&r;
#pragma unroll
    for (int k = 0; k < 4; k++) hr[k] = __hadd2(ha[k], hb[k]);
    return r;
}

// Accumulate 8 fp16 values (one 16B chunk) into fp32 accumulators.
__device__ __forceinline__ void acch(float* a, const ulonglong2 v)
{
    const __half2* h = (const __half2*)&v;
#pragma unroll
    for (int k = 0; k < 4; k++) {
        float2 f = __half22float2(h[k]);
        a[2 * k]     += f.x;
        a[2 * k + 1] += f.y;
    }
}

// One WARP per hyperedge (static assignment — R15 showed stealing serializes
// the per-edge prologue). fp16 row = 512B = 32 x 16B chunks: lane c owns chunk
// c (= 8 fp32 output columns). 8-member unroll keeps 8 independent row
// addresses in flight; HADD2 pairwise pre-add before fp32 convert+accumulate.
// 2-warp CTAs: reg-limited 42 warps/SM (66% occ) + fine backfill granularity.
__global__ void __launch_bounds__(NTHREADS)
agg_kernel(const int* __restrict__ nidx,   // [TOTAL]
           float*     __restrict__ out)    // [NUM_EDGES, 256]
{
    const int lane = threadIdx.x & 31;
    const int e    = blockIdx.x * WARPS_CTA + (threadIdx.x >> 5);

    const int lo = g_offs[e];
    const int hi = g_offs[e + 1];

    const ulonglong2* __restrict__ rows = (const ulonglong2*)g_emb_h; // 32 chunks/row

    float acc[8];
#pragma unroll
    for (int k = 0; k < 8; k++) acc[k] = 0.0f;

    // Pipelined index loads: prefetch next chunk while gathering current.
    int myidx = 0;
    if (lo + lane < hi) myidx = ldg_cs(nidx + lo + lane);

    for (int base = lo; base < hi; base += 32) {
        const int cnt = min(32, hi - base);
        const int cur = myidx;
        if (base + 32 + lane < hi) myidx = ldg_cs(nidx + base + 32 + lane);

        int j = 0;
        // 8 members per iteration -> 8 independent 16B gathers in flight/lane.
        for (; j + 8 <= cnt; j += 8) {
            const int n0 = __shfl_sync(0xffffffffu, cur, j);
            const int n1 = __shfl_sync(0xffffffffu, cur, j + 1);
            const int n2 = __shfl_sync(0xffffffffu, cur, j + 2);
            const int n3 = __shfl_sync(0xffffffffu, cur, j + 3);
            const int n4 = __shfl_sync(0xffffffffu, cur, j + 4);
            const int n5 = __shfl_sync(0xffffffffu, cur, j + 5);
            const int n6 = __shfl_sync(0xffffffffu, cur, j + 6);
            const int n7 = __shfl_sync(0xffffffffu, cur, j + 7);
            ulonglong2 v0 = ldg16(rows + (size_t)n0 * 32 + lane);
            ulonglong2 v1 = ldg16(rows + (size_t)n1 * 32 + lane);
            ulonglong2 v2 = ldg16(rows + (size_t)n2 * 32 + lane);
            ulonglong2 v3 = ldg16(rows + (size_t)n3 * 32 + lane);
            ulonglong2 v4 = ldg16(rows + (size_t)n4 * 32 + lane);
            ulonglong2 v5 = ldg16(rows + (size_t)n5 * 32 + lane);
            ulonglong2 v6 = ldg16(rows + (size_t)n6 * 32 + lane);
            ulonglong2 v7 = ldg16(rows + (size_t)n7 * 32 + lane);
            // fp16 pairwise pre-add, then convert+accumulate once per pair.
            acch(acc, hpair(v0, v1));
            acch(acc, hpair(v2, v3));
            acch(acc, hpair(v4, v5));
            acch(acc, hpair(v6, v7));
        }
        // Simple serial tail (keeps register pressure low).
        for (; j < cnt; j++) {
            const int n = __shfl_sync(0xffffffffu, cur, j);
            acch(acc, ldg16(rows + (size_t)n * 32 + lane));
        }
    }

    const int cnt = hi - lo;
    const float inv = 1.0f / (float)(cnt > 0 ? cnt : 1);
#pragma unroll
    for (int k = 0; k < 8; k++) acc[k] *= inv;

    // Lane c owns fp32 columns [8c, 8c+8) -> one 32B store.
    ulonglong4 r;
    float* f = (float*)&r;
#pragma unroll
    for (int k = 0; k < 8; k++) f[k] = acc[k];
    stg_cs8((ulonglong4*)out + (size_t)e * 32 + lane, r);
}

extern "C" void kernel_launch(void* const* d_in, const int* in_sizes, int n_in,
                              void* d_out, int out_size)
{
    const float* emb  = (const float*)d_in[0];
    const int*   nidx = (const int*)d_in[1];
    const int*   seg  = (const int*)d_in[2];
    float*       out  = (float*)d_out;
    const int total = in_sizes[1];

    const int bounds_blocks = (total + 255) / 256;
    prep_kernel<<<CONV_BLOCKS + bounds_blocks, 256>>>(emb, seg, total);
    agg_kernel<<<NUM_EDGES / WARPS_CTA, NTHREADS>>>(nidx, out);
}

// round 17
// speedup vs baseline: 1.2608x; 1.0363x over previous
#include <cuda_runtime.h>
#include <cuda_fp16.h>

#define EMBED_DIM   256
#define NUM_EDGES   16384
#define NUM_NODES   100000
#define NTHREADS    64                       // 2 warps/CTA: fine backfill
#define WARPS_CTA   (NTHREADS / 32)

#define CONV_GROUPS (NUM_NODES * EMBED_DIM / 8)   // 3,200,000 groups of 8 floats
#define CONV_BLOCKS (CONV_GROUPS / 256)           // 12,500

// fp16 shadow of the embedding table (51.2 MB) — sanctioned __device__ scratch.
__device__ __half g_emb_h[(size_t)NUM_NODES * EMBED_DIM];
// g_offs[e] = lower_bound(seg, e); g_offs[NUM_EDGES] = total.
__device__ int g_offs[NUM_EDGES + 1];

__device__ __forceinline__ unsigned h2_bits(__half2 h)
{
    unsigned u;
    *reinterpret_cast<__half2*>(&u) = h;
    return u;
}

// Fused prepass (measured-best config): blocks [0, CONV_BLOCKS) convert
// fp32 -> fp16 at 8 floats/thread; remaining blocks fill segment bounds.
__global__ void __launch_bounds__(256)
prep_kernel(const float* __restrict__ emb, const int* __restrict__ seg, int total)
{
    const int b = blockIdx.x;
    if (b < CONV_BLOCKS) {
        const int i = b * 256 + threadIdx.x;           // group of 8 floats
        const float4* src = (const float4*)emb;
        float4 a = __ldcs(src + 2 * (size_t)i);
        float4 c = __ldcs(src + 2 * (size_t)i + 1);
        uint4 o;
        o.x = h2_bits(__floats2half2_rn(a.x, a.y));
        o.y = h2_bits(__floats2half2_rn(a.z, a.w));
        o.z = h2_bits(__floats2half2_rn(c.x, c.y));
        o.w = h2_bits(__floats2half2_rn(c.z, c.w));
        ((uint4*)g_emb_h)[i] = o;
    } else {
        const int i = (b - CONV_BLOCKS) * 256 + threadIdx.x;
        if (i >= total) return;
        int cur = seg[i];
        if (i == 0) {
            for (int e = 0; e <= cur; e++) g_offs[e] = 0;
        } else {
            int prev = seg[i - 1];
            for (int e = prev + 1; e <= cur; e++) g_offs[e] = i;
        }
        if (i == total - 1) {
            for (int e = cur + 1; e <= NUM_EDGES; e++) g_offs[e] = total;
        }
    }
}

// 16-byte gather (non-volatile: let ptxas batch/hoist).
__device__ __forceinline__ ulonglong2 ldg16(const ulonglong2* p)
{
    ulonglong2 v;
    asm("ld.global.nc.v2.b64 {%0,%1}, [%2];"
        : "=l"(v.x), "=l"(v.y) : "l"(p));
    return v;
}

__device__ __forceinline__ int ldg_cs(const int* p)
{
    int v;
    asm volatile("ld.global.cs.b32 %0, [%1];" : "=r"(v) : "l"(p));
    return v;
}

__device__ __forceinline__ void stg_cs8(ulonglong4* p, const ulonglong4 v)
{
    asm volatile("st.global.cs.v4.b64 [%0], {%1,%2,%3,%4};"
                 :: "l"(p), "l"(v.x), "l"(v.y), "l"(v.z), "l"(v.w));
}

// Pairwise fp16 add of two 16B chunks (4 HADD2).
__device__ __forceinline__ ulonglong2 hpair(const ulonglong2 a, const ulonglong2 b)
{
    ulonglong2 r;
    const __half2* ha = (const __half2*)&a;
    const __half2* hb = (const __half2*)&b;
    __half2* hr = (__half2*)&r;
#pragma unroll
    for (int k = 0; k < 4; k++) hr[k] = __hadd2(ha[k], hb[k]);
    return r;
}

// Accumulate 8 fp16 values (one 16B chunk) into fp32 accumulators.
__device__ __forceinline__ void acch(float* a, const ulonglong2 v)
{
    const __half2* h = (const __half2*)&v;
#pragma unroll
    for (int k = 0; k < 4; k++) {
        float2 f = __half22float2(h[k]);
        a[2 * k]     += f.x;
        a[2 * k + 1] += f.y;
    }
}

// One WARP per hyperedge (static assignment). fp16 row = 512B = 32 x 16B
// chunks: lane c owns chunk c (= 8 fp32 output columns). 8-member unroll keeps
// 8 independent row addresses in flight; members pre-summed in a 4-deep fp16
// tree (HADD2) before the fp32 convert+accumulate — only 2 fp32 accumulate
// steps per 8 members.
__global__ void __launch_bounds__(NTHREADS)
agg_kernel(const int* __restrict__ nidx,   // [TOTAL]
           float*     __restrict__ out)    // [NUM_EDGES, 256]
{
    const int lane = threadIdx.x & 31;
    const int e    = blockIdx.x * WARPS_CTA + (threadIdx.x >> 5);

    const int lo = g_offs[e];
    const int hi = g_offs[e + 1];

    const ulonglong2* __restrict__ rows = (const ulonglong2*)g_emb_h; // 32 chunks/row

    float acc[8];
#pragma unroll
    for (int k = 0; k < 8; k++) acc[k] = 0.0f;

    // Pipelined index loads: prefetch next chunk while gathering current.
    int myidx = 0;
    if (lo + lane < hi) myidx = ldg_cs(nidx + lo + lane);

    for (int base = lo; base < hi; base += 32) {
        const int cnt = min(32, hi - base);
        const int cur = myidx;
        if (base + 32 + lane < hi) myidx = ldg_cs(nidx + base + 32 + lane);

        int j = 0;
        // 8 members per iteration -> 8 independent 16B gathers in flight/lane.
        for (; j + 8 <= cnt; j += 8) {
            const int n0 = __shfl_sync(0xffffffffu, cur, j);
            const int n1 = __shfl_sync(0xffffffffu, cur, j + 1);
            const int n2 = __shfl_sync(0xffffffffu, cur, j + 2);
            const int n3 = __shfl_sync(0xffffffffu, cur, j + 3);
            const int n4 = __shfl_sync(0xffffffffu, cur, j + 4);
            const int n5 = __shfl_sync(0xffffffffu, cur, j + 5);
            const int n6 = __shfl_sync(0xffffffffu, cur, j + 6);
            const int n7 = __shfl_sync(0xffffffffu, cur, j + 7);
            ulonglong2 v0 = ldg16(rows + (size_t)n0 * 32 + lane);
            ulonglong2 v1 = ldg16(rows + (size_t)n1 * 32 + lane);
            ulonglong2 v2 = ldg16(rows + (size_t)n2 * 32 + lane);
            ulonglong2 v3 = ldg16(rows + (size_t)n3 * 32 + lane);
            ulonglong2 v4 = ldg16(rows + (size_t)n4 * 32 + lane);
            ulonglong2 v5 = ldg16(rows + (size_t)n5 * 32 + lane);
            ulonglong2 v6 = ldg16(rows + (size_t)n6 * 32 + lane);
            ulonglong2 v7 = ldg16(rows + (size_t)n7 * 32 + lane);
            // 4-deep fp16 tree: (0+1)+(2+3), (4+5)+(6+7), then 2 fp32 steps.
            ulonglong2 s01   = hpair(v0, v1);
            ulonglong2 s23   = hpair(v2, v3);
            ulonglong2 s45   = hpair(v4, v5);
            ulonglong2 s67   = hpair(v6, v7);
            acch(acc, hpair(s01, s23));
            acch(acc, hpair(s45, s67));
        }
        // Simple serial tail (keeps register pressure low).
        for (; j < cnt; j++) {
            const int n = __shfl_sync(0xffffffffu, cur, j);
            acch(acc, ldg16(rows + (size_t)n * 32 + lane));
        }
    }

    const int cnt = hi - lo;
    const float inv = 1.0f / (float)(cnt > 0 ? cnt : 1);
#pragma unroll
    for (int k = 0; k < 8; k++) acc[k] *= inv;

    // Lane c owns fp32 columns [8c, 8c+8) -> one 32B store.
    ulonglong4 r;
    float* f = (float*)&r;
#pragma unroll
    for (int k = 0; k < 8; k++) f[k] = acc[k];
    stg_cs8((ulonglong4*)out + (size_t)e * 32 + lane, r);
}

extern "C" void kernel_launch(void* const* d_in, const int* in_sizes, int n_in,
                              void* d_out, int out_size)
{
    const float* emb  = (const float*)d_in[0];
    const int*   nidx = (const int*)d_in[1];
    const int*   seg  = (const int*)d_in[2];
    float*       out  = (float*)d_out;
    const int total = in_sizes[1];

    const int bounds_blocks = (total + 255) / 256;
    prep_kernel<<<CONV_BLOCKS + bounds_blocks, 256>>>(emb, seg, total);
    agg_kernel<<<NUM_EDGES / WARPS_CTA, NTHREADS>>>(nidx, out);
}